// round 2
// baseline (speedup 1.0000x reference)
#include <cuda_runtime.h>

// Problem constants
#define S_LEN 2048
#define B_SZ  128
#define H_SZ  128
#define G_SZ  384   // 3*H
#define C_SZ  10
#define TCH   16    // timesteps per GEMM CTA

// Scratch: xp (input projections, reused by both layers) and y0 (layer-0 output seq)
__device__ float g_xp[(size_t)S_LEN * B_SZ * G_SZ];   // [(t*B + b)*3H + g]
__device__ float g_y0[(size_t)S_LEN * B_SZ * H_SZ];   // [(t*B + b)*H + j]

// ---- packed dual-fp32 helpers -------------------------------------------
__device__ __forceinline__ unsigned long long fma2(unsigned long long a,
                                                   unsigned long long b,
                                                   unsigned long long c) {
    unsigned long long d;
    asm("fma.rn.f32x2 %0, %1, %2, %3;" : "=l"(d) : "l"(a), "l"(b), "l"(c));
    return d;
}
__device__ __forceinline__ unsigned long long add2(unsigned long long a,
                                                   unsigned long long b) {
    unsigned long long d;
    asm("add.rn.f32x2 %0, %1, %2;" : "=l"(d) : "l"(a), "l"(b));
    return d;
}
__device__ __forceinline__ float lo32(unsigned long long v) {
    return __uint_as_float((unsigned)(v & 0xffffffffull));
}
__device__ __forceinline__ float hi32(unsigned long long v) {
    return __uint_as_float((unsigned)(v >> 32));
}

// ---- cp.async helpers ----------------------------------------------------
__device__ __forceinline__ void cpasync16(void* smem, const void* gmem) {
    unsigned saddr = (unsigned)__cvta_generic_to_shared(smem);
    asm volatile("cp.async.cg.shared.global [%0], [%1], 16;"
                 :: "r"(saddr), "l"(gmem));
}
__device__ __forceinline__ void cpcommit() {
    asm volatile("cp.async.commit_group;" ::: "memory");
}
__device__ __forceinline__ void cpwait0() {
    asm volatile("cp.async.wait_group 0;" ::: "memory");
}

// ---------------------------------------------------------------------------
// Input-projection GEMM (persistent over TCH timesteps):
//   out[(t*B + b)*3H + g] = sum_d in[b*strideB + t*strideT + d] * W[g*H + d] + bias[g]
// Grid: (S_LEN/TCH, 2). Thread g holds its W row (128 fp32 = 64 u64) in regs.
// x tiles double-buffered in smem via cp.async; 2 batch rows / 4 chains per iter.
// ---------------------------------------------------------------------------
__global__ __launch_bounds__(384, 1)
void gemm_in_kernel(const float* __restrict__ in,
                    const float* __restrict__ W,
                    const float* __restrict__ bias,
                    float* __restrict__ out,
                    long strideB, long strideT)
{
    __shared__ __align__(16) float xs[2][64 * 128];

    const int tbase = blockIdx.x * TCH;
    const int b0    = blockIdx.y * 64;
    const int g     = threadIdx.x;

    // Weight row -> registers
    unsigned long long w[64];
    const unsigned long long* wrow =
        reinterpret_cast<const unsigned long long*>(W + (size_t)g * H_SZ);
#pragma unroll
    for (int i = 0; i < 64; i++) w[i] = wrow[i];
    const float bs = bias[g];

    // Stage tile for a given t into buffer buf (64 rows x 128 floats, 16B chunks)
    auto stage = [&](int buf, int t) {
        for (int i = threadIdx.x; i < 64 * 32; i += 384) {
            const int row = i >> 5;
            const int d4  = i & 31;
            const float* src = in + (size_t)(b0 + row) * strideB
                                  + (size_t)t * strideT + (size_t)d4 * 4;
            cpasync16(&xs[buf][row * 128 + d4 * 4], src);
        }
        cpcommit();
    };

    stage(0, tbase);
    cpwait0();
    __syncthreads();

    for (int tt = 0; tt < TCH; tt++) {
        const int t   = tbase + tt;
        const int cur = tt & 1;
        if (tt + 1 < TCH) stage(cur ^ 1, t + 1);

        for (int b = 0; b < 64; b += 2) {
            const ulonglong2* x0 =
                reinterpret_cast<const ulonglong2*>(&xs[cur][b * 128]);
            const ulonglong2* x1 = x0 + 32;   // next row (+128 floats)
            unsigned long long a0 = 0ull, a1 = 0ull, a2 = 0ull, a3 = 0ull;
#pragma unroll
            for (int i = 0; i < 32; i++) {
                const ulonglong2 q0 = x0[i];
                const ulonglong2 q1 = x1[i];
                a0 = fma2(q0.x, w[2 * i + 0], a0);
                a1 = fma2(q0.y, w[2 * i + 1], a1);
                a2 = fma2(q1.x, w[2 * i + 0], a2);
                a3 = fma2(q1.y, w[2 * i + 1], a3);
            }
            const unsigned long long s0 = add2(a0, a1);
            const unsigned long long s1 = add2(a2, a3);
            out[((size_t)t * B_SZ + (size_t)(b0 + b)) * G_SZ + g]     = lo32(s0) + hi32(s0) + bs;
            out[((size_t)t * B_SZ + (size_t)(b0 + b + 1)) * G_SZ + g] = lo32(s1) + hi32(s1) + bs;
        }

        cpwait0();
        __syncthreads();
    }
}

// ---------------------------------------------------------------------------
// Recurrent scan: one CTA per batch element, 384 threads (one per gate output).
// Thread g holds W_hh[g][:] in registers (64 u64). Per step:
//   hp[g] = h . W_hh[g] + b_hh[g]  (4 independent f32x2 chains, h via broadcast LDS)
//   threads 0..127 combine gates (x values prefetched from global one step ahead).
// write_y != 0  -> store h_t to g_y0 each step (layer 0)
// write_y == 0  -> fused output GEMM h_last @ W_out^T + b_out at the end
// ---------------------------------------------------------------------------
__global__ __launch_bounds__(384, 1)
void recur_kernel(const float* __restrict__ xp,
                  const float* __restrict__ W_hh,
                  const float* __restrict__ b_hh,
                  int write_y,
                  const float* __restrict__ W_out,
                  const float* __restrict__ b_out,
                  float* __restrict__ out)
{
    __shared__ __align__(16) float h_s[H_SZ];
    __shared__ float hp_s[G_SZ];

    const int b = blockIdx.x;
    const int g = threadIdx.x;

    unsigned long long w[64];
    const unsigned long long* wrow =
        reinterpret_cast<const unsigned long long*>(W_hh + (size_t)g * H_SZ);
#pragma unroll
    for (int i = 0; i < 64; i++) w[i] = wrow[i];
    const float bh = b_hh[g];

    // Gate threads prefetch their 3 x values for t=0
    const float* xb = xp + (size_t)b * G_SZ;
    float xr = 0.f, xz = 0.f, xn = 0.f;
    if (g < H_SZ) {
        xr = __ldg(xb + g);
        xz = __ldg(xb + H_SZ + g);
        xn = __ldg(xb + 2 * H_SZ + g);
        h_s[g] = 0.0f;
    }
    __syncthreads();

    for (int t = 0; t < S_LEN; t++) {
        // hp[g] = h . W_hh[g] : 4 independent f32x2 chains
        const ulonglong2* hq = reinterpret_cast<const ulonglong2*>(h_s);
        unsigned long long a0 = 0ull, a1 = 0ull, a2 = 0ull, a3 = 0ull;
#pragma unroll
        for (int i = 0; i < 16; i++) {
            const ulonglong2 q0 = hq[2 * i + 0];   // broadcast LDS.128
            const ulonglong2 q1 = hq[2 * i + 1];
            a0 = fma2(q0.x, w[4 * i + 0], a0);
            a1 = fma2(q0.y, w[4 * i + 1], a1);
            a2 = fma2(q1.x, w[4 * i + 2], a2);
            a3 = fma2(q1.y, w[4 * i + 3], a3);
        }
        const unsigned long long s01 = add2(add2(a0, a1), add2(a2, a3));
        hp_s[g] = lo32(s01) + hi32(s01) + bh;
        __syncthreads();

        if (g < H_SZ) {
            // Prefetch next step's x (issued early, consumed next iteration)
            float nxr = 0.f, nxz = 0.f, nxn = 0.f;
            if (t + 1 < S_LEN) {
                const float* p = xb + (size_t)(t + 1) * B_SZ * G_SZ;
                nxr = __ldg(p + g);
                nxz = __ldg(p + H_SZ + g);
                nxn = __ldg(p + 2 * H_SZ + g);
            }

            const float hr = hp_s[g];
            const float hz = hp_s[H_SZ + g];
            const float hn = hp_s[2 * H_SZ + g];
            const float pr = xr + hr;
            const float pz = xz + hz;
            const float r  = 1.0f / (1.0f + __expf(-pr));
            const float z  = 1.0f / (1.0f + __expf(-pz));
            const float ag = fmaf(r, hn, xn);
            // tanh(ag) = 2*sigmoid(2*ag) - 1
            const float sn = 1.0f / (1.0f + __expf(-2.0f * ag));
            const float n  = fmaf(2.0f, sn, -1.0f);
            const float hold = h_s[g];
            const float hnew = fmaf(z, hold - n, n);   // (1-z)*n + z*h
            h_s[g] = hnew;
            if (write_y)
                g_y0[((size_t)t * B_SZ + b) * H_SZ + g] = hnew;

            xr = nxr; xz = nxz; xn = nxn;
        }
        __syncthreads();
    }

    // Fused final linear layer (layer 1 only)
    if (!write_y && g < C_SZ) {
        float acc = b_out[g];
#pragma unroll 8
        for (int j = 0; j < H_SZ; j++)
            acc = fmaf(h_s[j], W_out[g * H_SZ + j], acc);
        out[b * C_SZ + g] = acc;
    }
}

// ---------------------------------------------------------------------------
// Launch: xp0 GEMM -> layer0 scan -> xp1 GEMM -> layer1 scan (+fused output)
// ---------------------------------------------------------------------------
extern "C" void kernel_launch(void* const* d_in, const int* in_sizes, int n_in,
                              void* d_out, int out_size)
{
    const float* x     = (const float*)d_in[0];
    const float* W_ih0 = (const float*)d_in[1];
    const float* W_hh0 = (const float*)d_in[2];
    const float* b_ih0 = (const float*)d_in[3];
    const float* b_hh0 = (const float*)d_in[4];
    const float* W_ih1 = (const float*)d_in[5];
    const float* W_hh1 = (const float*)d_in[6];
    const float* b_ih1 = (const float*)d_in[7];
    const float* b_hh1 = (const float*)d_in[8];
    const float* W_out = (const float*)d_in[9];
    const float* b_out = (const float*)d_in[10];
    float* out = (float*)d_out;

    void* xp_ptr = nullptr;
    void* y0_ptr = nullptr;
    cudaGetSymbolAddress(&xp_ptr, g_xp);
    cudaGetSymbolAddress(&y0_ptr, g_y0);
    float* xp = (float*)xp_ptr;
    float* y0 = (float*)y0_ptr;

    const dim3 gemm_grid(S_LEN / TCH, 2);

    // Layer 0 input projection: x is [B, S, D] -> strideB = S*D, strideT = D
    gemm_in_kernel<<<gemm_grid, 384>>>(x, W_ih0, b_ih0, xp,
                                       (long)S_LEN * H_SZ, (long)H_SZ);
    // Layer 0 recurrence (writes y0)
    recur_kernel<<<B_SZ, 384>>>(xp, W_hh0, b_hh0, 1, nullptr, nullptr, nullptr);

    // Layer 1 input projection: y0 is [(t*B + b)*H] -> strideB = H, strideT = B*H
    gemm_in_kernel<<<gemm_grid, 384>>>(y0, W_ih1, b_ih1, xp,
                                       (long)H_SZ, (long)B_SZ * H_SZ);
    // Layer 1 recurrence + fused output linear
    recur_kernel<<<B_SZ, 384>>>(xp, W_hh1, b_hh1, 0, W_out, b_out, out);
}

// round 3
// speedup vs baseline: 1.2090x; 1.2090x over previous
#include <cuda_runtime.h>

// Problem constants
#define S_LEN 2048
#define B_SZ  128
#define H_SZ  128
#define G_SZ  384   // 3*H
#define C_SZ  10
#define TCH   16    // timesteps per GEMM CTA

// Scratch: xp (input projections, reused by both layers) and y0 (layer-0 output seq)
__device__ float g_xp[(size_t)S_LEN * B_SZ * G_SZ];   // [(t*B + b)*3H + g]
__device__ float g_y0[(size_t)S_LEN * B_SZ * H_SZ];   // [(t*B + b)*H + j]

// ---- packed dual-fp32 helpers -------------------------------------------
__device__ __forceinline__ unsigned long long fma2(unsigned long long a,
                                                   unsigned long long b,
                                                   unsigned long long c) {
    unsigned long long d;
    asm("fma.rn.f32x2 %0, %1, %2, %3;" : "=l"(d) : "l"(a), "l"(b), "l"(c));
    return d;
}
__device__ __forceinline__ unsigned long long add2(unsigned long long a,
                                                   unsigned long long b) {
    unsigned long long d;
    asm("add.rn.f32x2 %0, %1, %2;" : "=l"(d) : "l"(a), "l"(b));
    return d;
}
__device__ __forceinline__ float lo32(unsigned long long v) {
    return __uint_as_float((unsigned)(v & 0xffffffffull));
}
__device__ __forceinline__ float hi32(unsigned long long v) {
    return __uint_as_float((unsigned)(v >> 32));
}

// ---- cp.async helpers ----------------------------------------------------
__device__ __forceinline__ void cpasync16(void* smem, const void* gmem) {
    unsigned saddr = (unsigned)__cvta_generic_to_shared(smem);
    asm volatile("cp.async.cg.shared.global [%0], [%1], 16;"
                 :: "r"(saddr), "l"(gmem));
}
__device__ __forceinline__ void cpcommit() {
    asm volatile("cp.async.commit_group;" ::: "memory");
}
__device__ __forceinline__ void cpwait0() {
    asm volatile("cp.async.wait_group 0;" ::: "memory");
}

// ---------------------------------------------------------------------------
// Input-projection GEMM (persistent over TCH timesteps):
//   out[(t*B + b)*3H + g] = sum_d in[b*strideB + t*strideT + d] * W[g*H + d] + bias[g]
// Grid: (S_LEN/TCH, 2). Thread g holds its W row (128 fp32 = 64 u64) in regs.
// x tiles double-buffered in smem via cp.async; 2 batch rows / 4 chains per iter.
// ---------------------------------------------------------------------------
__global__ __launch_bounds__(384, 1)
void gemm_in_kernel(const float* __restrict__ in,
                    const float* __restrict__ W,
                    const float* __restrict__ bias,
                    float* __restrict__ out,
                    long strideB, long strideT)
{
    __shared__ __align__(16) float xs[2][64 * 128];

    const int tbase = blockIdx.x * TCH;
    const int b0    = blockIdx.y * 64;
    const int g     = threadIdx.x;

    // Weight row -> registers
    unsigned long long w[64];
    const unsigned long long* wrow =
        reinterpret_cast<const unsigned long long*>(W + (size_t)g * H_SZ);
#pragma unroll
    for (int i = 0; i < 64; i++) w[i] = wrow[i];
    const float bs = bias[g];

    // Stage tile for a given t into buffer buf (64 rows x 128 floats, 16B chunks)
    auto stage = [&](int buf, int t) {
        for (int i = threadIdx.x; i < 64 * 32; i += 384) {
            const int row = i >> 5;
            const int d4  = i & 31;
            const float* src = in + (size_t)(b0 + row) * strideB
                                  + (size_t)t * strideT + (size_t)d4 * 4;
            cpasync16(&xs[buf][row * 128 + d4 * 4], src);
        }
        cpcommit();
    };

    stage(0, tbase);
    cpwait0();
    __syncthreads();

    for (int tt = 0; tt < TCH; tt++) {
        const int t   = tbase + tt;
        const int cur = tt & 1;
        if (tt + 1 < TCH) stage(cur ^ 1, t + 1);

        for (int b = 0; b < 64; b += 2) {
            const ulonglong2* x0 =
                reinterpret_cast<const ulonglong2*>(&xs[cur][b * 128]);
            const ulonglong2* x1 = x0 + 32;   // next row (+128 floats)
            unsigned long long a0 = 0ull, a1 = 0ull, a2 = 0ull, a3 = 0ull;
#pragma unroll
            for (int i = 0; i < 32; i++) {
                const ulonglong2 q0 = x0[i];
                const ulonglong2 q1 = x1[i];
                a0 = fma2(q0.x, w[2 * i + 0], a0);
                a1 = fma2(q0.y, w[2 * i + 1], a1);
                a2 = fma2(q1.x, w[2 * i + 0], a2);
                a3 = fma2(q1.y, w[2 * i + 1], a3);
            }
            const unsigned long long s0 = add2(a0, a1);
            const unsigned long long s1 = add2(a2, a3);
            out[((size_t)t * B_SZ + (size_t)(b0 + b)) * G_SZ + g]     = lo32(s0) + hi32(s0) + bs;
            out[((size_t)t * B_SZ + (size_t)(b0 + b + 1)) * G_SZ + g] = lo32(s1) + hi32(s1) + bs;
        }

        cpwait0();
        __syncthreads();
    }
}

// ---------------------------------------------------------------------------
// Recurrent scan: one CTA per batch element, 384 threads.
//   Warps 0-3  (g in [0,128))  : r-gate dot (hr kept in registers) + gate combine.
//   Warps 4-11 (g in [128,384)): z/n-gate dots -> hp_s, then single bar.sync wait.
// Barrier protocol (named, counting):
//   bar 1 (384): producers arrive after STS hp; gate warps sync (wait hp ready)
//   bar 2 (384): gate warps arrive after STS h;  producers sync (wait h ready)
//   bar 3 (128): gate warps internal sync before re-reading h_s
// write_y != 0 -> store h_t to g_y0 each step (layer 0)
// write_y == 0 -> fused output GEMM h_last @ W_out^T + b_out at the end
// ---------------------------------------------------------------------------
__global__ __launch_bounds__(384, 1)
void recur_kernel(const float* __restrict__ xp,
                  const float* __restrict__ W_hh,
                  const float* __restrict__ b_hh,
                  int write_y,
                  const float* __restrict__ W_out,
                  const float* __restrict__ b_out,
                  float* __restrict__ out)
{
    __shared__ __align__(16) float h_s[H_SZ];
    __shared__ float hp_s[2 * H_SZ];   // z then n projections

    const int b = blockIdx.x;
    const int g = threadIdx.x;

    unsigned long long w[64];
    const unsigned long long* wrow =
        reinterpret_cast<const unsigned long long*>(W_hh + (size_t)g * H_SZ);
#pragma unroll
    for (int i = 0; i < 64; i++) w[i] = wrow[i];
    const float bh = b_hh[g];

    const float* xb = xp + (size_t)b * G_SZ;

    if (g < H_SZ) {
        // ---------------- gate warps ----------------
        float xr = __ldg(xb + g);
        float xz = __ldg(xb + H_SZ + g);
        float xn = __ldg(xb + 2 * H_SZ + g);
        float hreg = 0.0f;
        h_s[g] = 0.0f;
        __syncthreads();

        float* y0row = g_y0 + (size_t)b * H_SZ + g;

        for (int t = 0; t < S_LEN; t++) {
            const bool more = (t + 1 < S_LEN);
            // Prefetch next step's x early (hidden under the dot + barrier)
            float nxr = 0.f, nxz = 0.f, nxn = 0.f;
            if (more) {
                const float* p = xb + (size_t)(t + 1) * B_SZ * G_SZ;
                nxr = __ldg(p + g);
                nxz = __ldg(p + H_SZ + g);
                nxn = __ldg(p + 2 * H_SZ + g);
            }

            // hr = h . W_hh[g] (r-gate row) : 4 independent f32x2 chains
            const ulonglong2* hq = reinterpret_cast<const ulonglong2*>(h_s);
            unsigned long long a0 = 0ull, a1 = 0ull, a2 = 0ull, a3 = 0ull;
#pragma unroll
            for (int i = 0; i < 16; i++) {
                const ulonglong2 q0 = hq[2 * i + 0];
                const ulonglong2 q1 = hq[2 * i + 1];
                a0 = fma2(q0.x, w[4 * i + 0], a0);
                a1 = fma2(q0.y, w[4 * i + 1], a1);
                a2 = fma2(q1.x, w[4 * i + 2], a2);
                a3 = fma2(q1.y, w[4 * i + 3], a3);
            }
            const unsigned long long sr = add2(add2(a0, a1), add2(a2, a3));
            const float hr = lo32(sr) + hi32(sr) + bh;

            // Wait for producers' hp (z, n)
            asm volatile("bar.sync 1, 384;" ::: "memory");

            const float hz = hp_s[g];
            const float hn = hp_s[H_SZ + g];
            const float pr = xr + hr;
            const float pz = xz + hz;
            const float r  = 1.0f / (1.0f + __expf(-pr));
            const float z  = 1.0f / (1.0f + __expf(-pz));
            const float ag = fmaf(r, hn, xn);
            const float sn = 1.0f / (1.0f + __expf(-2.0f * ag));
            const float n  = fmaf(2.0f, sn, -1.0f);        // tanh(ag)
            const float hnew = fmaf(z, hreg - n, n);        // (1-z)*n + z*h
            hreg = hnew;
            h_s[g] = hnew;
            if (write_y)
                y0row[(size_t)t * B_SZ * H_SZ] = hnew;

            if (more) {
                // Release producers (h ready), then sync gate warps before
                // re-reading h_s in the next dot.
                asm volatile("bar.arrive 2, 384;" ::: "memory");
                asm volatile("bar.sync 3, 128;" ::: "memory");
            }
            xr = nxr; xz = nxz; xn = nxn;
        }
    } else {
        // ---------------- producer warps (z, n dots) ----------------
        const int gi = g - H_SZ;
        __syncthreads();

        for (int t = 0; t < S_LEN; t++) {
            const ulonglong2* hq = reinterpret_cast<const ulonglong2*>(h_s);
            unsigned long long a0 = 0ull, a1 = 0ull, a2 = 0ull, a3 = 0ull;
#pragma unroll
            for (int i = 0; i < 16; i++) {
                const ulonglong2 q0 = hq[2 * i + 0];
                const ulonglong2 q1 = hq[2 * i + 1];
                a0 = fma2(q0.x, w[4 * i + 0], a0);
                a1 = fma2(q0.y, w[4 * i + 1], a1);
                a2 = fma2(q1.x, w[4 * i + 2], a2);
                a3 = fma2(q1.y, w[4 * i + 3], a3);
            }
            const unsigned long long s = add2(add2(a0, a1), add2(a2, a3));
            hp_s[gi] = lo32(s) + hi32(s) + bh;

            // Signal hp ready; wait for new h (except after the last step)
            asm volatile("bar.arrive 1, 384;" ::: "memory");
            if (t + 1 < S_LEN)
                asm volatile("bar.sync 2, 384;" ::: "memory");
        }
    }

    __syncthreads();

    // Fused final linear layer (layer 1 only)
    if (!write_y && g < C_SZ) {
        float acc = b_out[g];
#pragma unroll 8
        for (int j = 0; j < H_SZ; j++)
            acc = fmaf(h_s[j], W_out[g * H_SZ + j], acc);
        out[b * C_SZ + g] = acc;
    }
}

// ---------------------------------------------------------------------------
// Launch: xp0 GEMM -> layer0 scan -> xp1 GEMM -> layer1 scan (+fused output)
// ---------------------------------------------------------------------------
extern "C" void kernel_launch(void* const* d_in, const int* in_sizes, int n_in,
                              void* d_out, int out_size)
{
    const float* x     = (const float*)d_in[0];
    const float* W_ih0 = (const float*)d_in[1];
    const float* W_hh0 = (const float*)d_in[2];
    const float* b_ih0 = (const float*)d_in[3];
    const float* b_hh0 = (const float*)d_in[4];
    const float* W_ih1 = (const float*)d_in[5];
    const float* W_hh1 = (const float*)d_in[6];
    const float* b_ih1 = (const float*)d_in[7];
    const float* b_hh1 = (const float*)d_in[8];
    const float* W_out = (const float*)d_in[9];
    const float* b_out = (const float*)d_in[10];
    float* out = (float*)d_out;

    void* xp_ptr = nullptr;
    void* y0_ptr = nullptr;
    cudaGetSymbolAddress(&xp_ptr, g_xp);
    cudaGetSymbolAddress(&y0_ptr, g_y0);
    float* xp = (float*)xp_ptr;
    float* y0 = (float*)y0_ptr;

    const dim3 gemm_grid(S_LEN / TCH, 2);

    // Layer 0 input projection: x is [B, S, D] -> strideB = S*D, strideT = D
    gemm_in_kernel<<<gemm_grid, 384>>>(x, W_ih0, b_ih0, xp,
                                       (long)S_LEN * H_SZ, (long)H_SZ);
    // Layer 0 recurrence (writes y0)
    recur_kernel<<<B_SZ, 384>>>(xp, W_hh0, b_hh0, 1, nullptr, nullptr, nullptr);

    // Layer 1 input projection: y0 is [(t*B + b)*H] -> strideB = H, strideT = B*H
    gemm_in_kernel<<<gemm_grid, 384>>>(y0, W_ih1, b_ih1, xp,
                                       (long)H_SZ, (long)B_SZ * H_SZ);
    // Layer 1 recurrence + fused output linear
    recur_kernel<<<B_SZ, 384>>>(xp, W_hh1, b_hh1, 0, W_out, b_out, out);
}

// round 5
// speedup vs baseline: 1.2535x; 1.0368x over previous
#include <cuda_runtime.h>

// Problem constants
#define S_LEN 2048
#define B_SZ  128
#define H_SZ  128
#define G_SZ  384   // 3*H
#define C_SZ  10
#define TCH   16    // timesteps per GEMM CTA

// Scratch: xp (input projections, reused by both layers) and y0 (layer-0 output seq)
__device__ float g_xp[(size_t)S_LEN * B_SZ * G_SZ];   // [(t*B + b)*3H + g]
__device__ float g_y0[(size_t)S_LEN * B_SZ * H_SZ];   // [(t*B + b)*H + j]

// ---- packed dual-fp32 helpers -------------------------------------------
__device__ __forceinline__ unsigned long long fma2(unsigned long long a,
                                                   unsigned long long b,
                                                   unsigned long long c) {
    unsigned long long d;
    asm("fma.rn.f32x2 %0, %1, %2, %3;" : "=l"(d) : "l"(a), "l"(b), "l"(c));
    return d;
}
__device__ __forceinline__ unsigned long long add2(unsigned long long a,
                                                   unsigned long long b) {
    unsigned long long d;
    asm("add.rn.f32x2 %0, %1, %2;" : "=l"(d) : "l"(a), "l"(b));
    return d;
}
__device__ __forceinline__ float lo32(unsigned long long v) {
    return __uint_as_float((unsigned)(v & 0xffffffffull));
}
__device__ __forceinline__ float hi32(unsigned long long v) {
    return __uint_as_float((unsigned)(v >> 32));
}

// ---- cp.async helpers ----------------------------------------------------
__device__ __forceinline__ void cpasync16(void* smem, const void* gmem) {
    unsigned saddr = (unsigned)__cvta_generic_to_shared(smem);
    asm volatile("cp.async.cg.shared.global [%0], [%1], 16;"
                 :: "r"(saddr), "l"(gmem));
}
__device__ __forceinline__ void cpcommit() {
    asm volatile("cp.async.commit_group;" ::: "memory");
}
__device__ __forceinline__ void cpwait0() {
    asm volatile("cp.async.wait_group 0;" ::: "memory");
}

// ---------------------------------------------------------------------------
// Input-projection GEMM (persistent over TCH timesteps) — unchanged (best so far).
//   out[(t*B + b)*3H + g] = sum_d in[b*strideB + t*strideT + d] * W[g*H + d] + bias[g]
// ---------------------------------------------------------------------------
__global__ __launch_bounds__(384, 1)
void gemm_in_kernel(const float* __restrict__ in,
                    const float* __restrict__ W,
                    const float* __restrict__ bias,
                    float* __restrict__ out,
                    long strideB, long strideT)
{
    __shared__ __align__(16) float xs[2][64 * 128];

    const int tbase = blockIdx.x * TCH;
    const int b0    = blockIdx.y * 64;
    const int g     = threadIdx.x;

    unsigned long long w[64];
    const unsigned long long* wrow =
        reinterpret_cast<const unsigned long long*>(W + (size_t)g * H_SZ);
#pragma unroll
    for (int i = 0; i < 64; i++) w[i] = wrow[i];
    const float bs = bias[g];

    auto stage = [&](int buf, int t) {
        for (int i = threadIdx.x; i < 64 * 32; i += 384) {
            const int row = i >> 5;
            const int d4  = i & 31;
            const float* src = in + (size_t)(b0 + row) * strideB
                                  + (size_t)t * strideT + (size_t)d4 * 4;
            cpasync16(&xs[buf][row * 128 + d4 * 4], src);
        }
        cpcommit();
    };

    stage(0, tbase);
    cpwait0();
    __syncthreads();

    for (int tt = 0; tt < TCH; tt++) {
        const int t   = tbase + tt;
        const int cur = tt & 1;
        if (tt + 1 < TCH) stage(cur ^ 1, t + 1);

        for (int b = 0; b < 64; b += 2) {
            const ulonglong2* x0 =
                reinterpret_cast<const ulonglong2*>(&xs[cur][b * 128]);
            const ulonglong2* x1 = x0 + 32;
            unsigned long long a0 = 0ull, a1 = 0ull, a2 = 0ull, a3 = 0ull;
#pragma unroll
            for (int i = 0; i < 32; i++) {
                const ulonglong2 q0 = x0[i];
                const ulonglong2 q1 = x1[i];
                a0 = fma2(q0.x, w[2 * i + 0], a0);
                a1 = fma2(q0.y, w[2 * i + 1], a1);
                a2 = fma2(q1.x, w[2 * i + 0], a2);
                a3 = fma2(q1.y, w[2 * i + 1], a3);
            }
            const unsigned long long s0 = add2(a0, a1);
            const unsigned long long s1 = add2(a2, a3);
            out[((size_t)t * B_SZ + (size_t)(b0 + b)) * G_SZ + g]     = lo32(s0) + hi32(s0) + bs;
            out[((size_t)t * B_SZ + (size_t)(b0 + b + 1)) * G_SZ + g] = lo32(s1) + hi32(s1) + bs;
        }

        cpwait0();
        __syncthreads();
    }
}

// ---------------------------------------------------------------------------
// Recurrent scan: one CTA per batch element, 256 threads.
// Thread tid = 2*j + p computes the p-th HALF (64 elems = 16 ulonglong2) of
// ALL THREE gate rows for output j. Halves combined via shfl_xor(1) — no hp
// smem round-trip. Gate math split across the lane pair (even: r+tanh, odd: z).
// h double-buffered in smem -> ONE __syncthreads per step.
// ---------------------------------------------------------------------------
__global__ __launch_bounds__(256, 1)
void recur_kernel(const float* __restrict__ xp,
                  const float* __restrict__ W_hh,
                  const float* __restrict__ b_hh,
                  int write_y,
                  const float* __restrict__ W_out,
                  const float* __restrict__ b_out,
                  float* __restrict__ out)
{
    __shared__ __align__(16) float h_s[2][H_SZ];

    const int b   = blockIdx.x;
    const int tid = threadIdx.x;
    const int j   = tid >> 1;
    const int p   = tid & 1;

    // Weight half-rows -> registers (3 x 32 u64 = 192 regs of weights)
    unsigned long long wr[32], wz[32], wn[32];
    {
        const unsigned long long* rp = reinterpret_cast<const unsigned long long*>(
            W_hh + (size_t)j * H_SZ + p * 64);
        const unsigned long long* zp = reinterpret_cast<const unsigned long long*>(
            W_hh + (size_t)(H_SZ + j) * H_SZ + p * 64);
        const unsigned long long* np = reinterpret_cast<const unsigned long long*>(
            W_hh + (size_t)(2 * H_SZ + j) * H_SZ + p * 64);
#pragma unroll
        for (int i = 0; i < 32; i++) { wr[i] = rp[i]; wz[i] = zp[i]; wn[i] = np[i]; }
    }
    const float br = b_hh[j];
    const float bz = b_hh[H_SZ + j];
    const float bn = b_hh[2 * H_SZ + j];

    const float* xb = xp + (size_t)b * G_SZ;
    // even lane holds xr, xn; odd lane holds xz
    float xr = 0.f, xn = 0.f, xz = 0.f;
    if (p == 0) { xr = __ldg(xb + j); xn = __ldg(xb + 2 * H_SZ + j); }
    else        { xz = __ldg(xb + H_SZ + j); }

    float hreg = 0.0f;                 // live h value (even lanes)
    if (tid < H_SZ) h_s[0][tid] = 0.0f;
    __syncthreads();

    float* y0p = g_y0 + (size_t)b * H_SZ + j;

    for (int t = 0; t < S_LEN; t++) {
        const int cur = t & 1;
        const int nxt = cur ^ 1;

        // Prefetch next step's x (consumed after ~1 full step -> hidden)
        float nxr = 0.f, nxn = 0.f, nxz = 0.f;
        if (t + 1 < S_LEN) {
            const float* q = xb + (size_t)(t + 1) * B_SZ * G_SZ;
            if (p == 0) { nxr = __ldg(q + j); nxn = __ldg(q + 2 * H_SZ + j); }
            else        { nxz = __ldg(q + H_SZ + j); }
        }

        // Half-dots: 3 gates x 64 elems = 16 ulonglong2, 6 independent chains
        const ulonglong2* hq =
            reinterpret_cast<const ulonglong2*>(&h_s[cur][p * 64]);
        unsigned long long ar0 = 0ull, ar1 = 0ull;
        unsigned long long az0 = 0ull, az1 = 0ull;
        unsigned long long an0 = 0ull, an1 = 0ull;
#pragma unroll
        for (int i = 0; i < 16; i++) {          // FIXED: 16 (was 8) -> full 64 floats
            const ulonglong2 q = hq[i];
            ar0 = fma2(q.x, wr[2 * i + 0], ar0);
            ar1 = fma2(q.y, wr[2 * i + 1], ar1);
            az0 = fma2(q.x, wz[2 * i + 0], az0);
            az1 = fma2(q.y, wz[2 * i + 1], az1);
            an0 = fma2(q.x, wn[2 * i + 0], an0);
            an1 = fma2(q.y, wn[2 * i + 1], an1);
        }
        const unsigned long long sr2 = add2(ar0, ar1);
        const unsigned long long sz2 = add2(az0, az1);
        const unsigned long long sn2 = add2(an0, an1);
        float srh = lo32(sr2) + hi32(sr2);
        float szh = lo32(sz2) + hi32(sz2);
        float snh = lo32(sn2) + hi32(sn2);

        // Combine halves (lane pair 2j <-> 2j+1)
        srh += __shfl_xor_sync(0xffffffffu, srh, 1);
        szh += __shfl_xor_sync(0xffffffffu, szh, 1);
        snh += __shfl_xor_sync(0xffffffffu, snh, 1);

        // Gate math split across the pair:
        //   even lane: r = sigmoid(xr + srh + br), tanh path
        //   odd  lane: z = sigmoid(xz + szh + bz), shfl'd to even
        const float pr = xr + srh + br;     // garbage on odd (unused)
        const float pz = xz + szh + bz;     // garbage on even (replaced by shfl)
        const float rg = 1.0f / (1.0f + __expf(-pr));
        const float zg = 1.0f / (1.0f + __expf(-pz));
        const float z  = __shfl_xor_sync(0xffffffffu, zg, 1);  // even <- odd's z

        if (p == 0) {
            const float hn = snh + bn;
            const float ag = fmaf(rg, hn, xn);
            const float sn = 1.0f / (1.0f + __expf(-2.0f * ag));
            const float n  = fmaf(2.0f, sn, -1.0f);            // tanh(ag)
            const float hnew = fmaf(z, hreg - n, n);           // (1-z)*n + z*h
            hreg = hnew;
            h_s[nxt][j] = hnew;
            if (write_y)
                y0p[(size_t)t * B_SZ * H_SZ] = hnew;
        }
        __syncthreads();

        xr = nxr; xn = nxn; xz = nxz;
    }

    // Fused final linear layer (layer 1 only); after 2048 steps final h is in h_s[0]
    if (!write_y && tid < C_SZ) {
        float acc = b_out[tid];
#pragma unroll 8
        for (int k = 0; k < H_SZ; k++)
            acc = fmaf(h_s[0][k], W_out[tid * H_SZ + k], acc);
        out[b * C_SZ + tid] = acc;
    }
}

// ---------------------------------------------------------------------------
// Launch: xp0 GEMM -> layer0 scan -> xp1 GEMM -> layer1 scan (+fused output)
// ---------------------------------------------------------------------------
extern "C" void kernel_launch(void* const* d_in, const int* in_sizes, int n_in,
                              void* d_out, int out_size)
{
    const float* x     = (const float*)d_in[0];
    const float* W_ih0 = (const float*)d_in[1];
    const float* W_hh0 = (const float*)d_in[2];
    const float* b_ih0 = (const float*)d_in[3];
    const float* b_hh0 = (const float*)d_in[4];
    const float* W_ih1 = (const float*)d_in[5];
    const float* W_hh1 = (const float*)d_in[6];
    const float* b_ih1 = (const float*)d_in[7];
    const float* b_hh1 = (const float*)d_in[8];
    const float* W_out = (const float*)d_in[9];
    const float* b_out = (const float*)d_in[10];
    float* out = (float*)d_out;

    void* xp_ptr = nullptr;
    void* y0_ptr = nullptr;
    cudaGetSymbolAddress(&xp_ptr, g_xp);
    cudaGetSymbolAddress(&y0_ptr, g_y0);
    float* xp = (float*)xp_ptr;
    float* y0 = (float*)y0_ptr;

    const dim3 gemm_grid(S_LEN / TCH, 2);

    // Layer 0 input projection: x is [B, S, D] -> strideB = S*D, strideT = D
    gemm_in_kernel<<<gemm_grid, 384>>>(x, W_ih0, b_ih0, xp,
                                       (long)S_LEN * H_SZ, (long)H_SZ);
    // Layer 0 recurrence (writes y0)
    recur_kernel<<<B_SZ, 256>>>(xp, W_hh0, b_hh0, 1, nullptr, nullptr, nullptr);

    // Layer 1 input projection: y0 is [(t*B + b)*H] -> strideB = H, strideT = B*H
    gemm_in_kernel<<<gemm_grid, 384>>>(y0, W_ih1, b_ih1, xp,
                                       (long)H_SZ, (long)B_SZ * H_SZ);
    // Layer 1 recurrence + fused output linear
    recur_kernel<<<B_SZ, 256>>>(xp, W_hh1, b_hh1, 0, W_out, b_out, out);
}

// round 7
// speedup vs baseline: 1.5186x; 1.2115x over previous
#include <cuda_runtime.h>
#include <cuda_bf16.h>
#include <cstdint>

// Problem constants
#define S_LEN 2048
#define B_SZ  128
#define H_SZ  128
#define G_SZ  384   // 3*H
#define C_SZ  10
#define TCH_T 16    // timesteps per GEMM CTA

// Scratch: xp (input projections, reused by both layers) and y0 (layer-0 output seq)
__device__ float g_xp[(size_t)S_LEN * B_SZ * G_SZ];   // [(t*B + b)*3H + g]
__device__ float g_y0[(size_t)S_LEN * B_SZ * H_SZ];   // [(t*B + b)*H + j]

// ---- packed dual-fp32 helpers -------------------------------------------
__device__ __forceinline__ unsigned long long fma2(unsigned long long a,
                                                   unsigned long long b,
                                                   unsigned long long c) {
    unsigned long long d;
    asm("fma.rn.f32x2 %0, %1, %2, %3;" : "=l"(d) : "l"(a), "l"(b), "l"(c));
    return d;
}
__device__ __forceinline__ unsigned long long add2(unsigned long long a,
                                                   unsigned long long b) {
    unsigned long long d;
    asm("add.rn.f32x2 %0, %1, %2;" : "=l"(d) : "l"(a), "l"(b));
    return d;
}
__device__ __forceinline__ float lo32(unsigned long long v) {
    return __uint_as_float((unsigned)(v & 0xffffffffull));
}
__device__ __forceinline__ float hi32(unsigned long long v) {
    return __uint_as_float((unsigned)(v >> 32));
}

// ---- mma.sync / ldmatrix helpers (plain sm_80+ features, no 'a'-gating) ---
__device__ __forceinline__ uint32_t smem_u32(const void* p) {
    uint32_t a;
    asm("{ .reg .u64 t; cvta.to.shared.u64 t, %1; cvt.u32.u64 %0, t; }"
        : "=r"(a) : "l"(p));
    return a;
}
__device__ __forceinline__ void ldmx4(uint32_t* r, uint32_t addr) {
    asm volatile("ldmatrix.sync.aligned.m8n8.x4.shared.b16 {%0,%1,%2,%3}, [%4];"
                 : "=r"(r[0]), "=r"(r[1]), "=r"(r[2]), "=r"(r[3]) : "r"(addr));
}
__device__ __forceinline__ void mma_bf16(float* c, const uint32_t* a,
                                         uint32_t b0, uint32_t b1) {
    asm volatile(
        "mma.sync.aligned.m16n8k16.row.col.f32.bf16.bf16.f32 "
        "{%0,%1,%2,%3}, {%4,%5,%6,%7}, {%8,%9}, {%0,%1,%2,%3};"
        : "+f"(c[0]), "+f"(c[1]), "+f"(c[2]), "+f"(c[3])
        : "r"(a[0]), "r"(a[1]), "r"(a[2]), "r"(a[3]), "r"(b0), "r"(b1));
}

// Split one float4 into bf16 hi + lo pairs (packed as uint2 = 4 bf16)
__device__ __forceinline__ void split4(float4 v, uint2& hi, uint2& lo) {
    __nv_bfloat162 h01 = __floats2bfloat162_rn(v.x, v.y);
    __nv_bfloat162 h23 = __floats2bfloat162_rn(v.z, v.w);
    const float r0 = v.x - __bfloat162float(h01.x);
    const float r1 = v.y - __bfloat162float(h01.y);
    const float r2 = v.z - __bfloat162float(h23.x);
    const float r3 = v.w - __bfloat162float(h23.y);
    __nv_bfloat162 l01 = __floats2bfloat162_rn(r0, r1);
    __nv_bfloat162 l23 = __floats2bfloat162_rn(r2, r3);
    hi = make_uint2(*reinterpret_cast<uint32_t*>(&h01), *reinterpret_cast<uint32_t*>(&h23));
    lo = make_uint2(*reinterpret_cast<uint32_t*>(&l01), *reinterpret_cast<uint32_t*>(&l23));
}

// SMEM layout (bytes): bias + 4 bf16 tiles [128 rows x 128 cols], pitch 272 B
#define PITCHB 272
#define TILEB  (128 * PITCHB)          // 34816
#define SM_BIAS 0
#define SM_XHI  512
#define SM_XLO  (SM_XHI + TILEB)
#define SM_WHI  (SM_XLO + TILEB)
#define SM_WLO  (SM_WHI + TILEB)
#define SM_TOT  (SM_WLO + TILEB)       // 139776

// ---------------------------------------------------------------------------
// Tensor-core input-projection GEMM via mma.sync (bf16 hi/lo split, fp32 acc):
//   out[(t*B + b)*3H + g0 + n] = sum_d in[b*strideB + t*strideT + d] * W[(g0+n)*H + d] + bias
// Grid (S_LEN/TCH_T, 3), 256 threads (8 warps, warp tile M64 x N32).
// ---------------------------------------------------------------------------
__global__ __launch_bounds__(256, 1)
void gemm_mma_kernel(const float* __restrict__ in,
                     const float* __restrict__ W,
                     const float* __restrict__ bias,
                     float* __restrict__ out,
                     long strideB, long strideT)
{
    extern __shared__ __align__(16) char smem[];
    const uint32_t sb = smem_u32(smem);
    float* sbias = reinterpret_cast<float*>(smem + SM_BIAS);

    const int tid  = threadIdx.x;
    const int w    = tid >> 5;
    const int lane = tid & 31;
    const int tbase = blockIdx.x * TCH_T;
    const int g0    = blockIdx.y * 128;

    // Stage W chunk [128 gates x 128 d] hi/lo + bias (once per CTA)
    if (tid < 128) sbias[tid] = bias[g0 + tid];
    for (int i = tid; i < 128 * 32; i += 256) {
        const int row = i >> 5, c4 = i & 31;
        const float4 v = *reinterpret_cast<const float4*>(
            W + (size_t)(g0 + row) * H_SZ + c4 * 4);
        uint2 hi, lo;
        split4(v, hi, lo);
        const int off = row * PITCHB + c4 * 8;
        *reinterpret_cast<uint2*>(smem + SM_WHI + off) = hi;
        *reinterpret_cast<uint2*>(smem + SM_WLO + off) = lo;
    }

    // Warp tiling: mBase in {0,64}, nBase in {0,32,64,96}
    const int mBase = (w & 1) * 64;
    const int nBase = (w >> 1) * 32;

    // Per-lane ldmatrix row-address offsets (relative to tile base, bytes)
    uint32_t aoff[4];
#pragma unroll
    for (int mt = 0; mt < 4; mt++)
        aoff[mt] = (uint32_t)((mBase + mt * 16 + (lane & 15)) * PITCHB
                              + (lane >> 4) * 16);
    uint32_t boff[2];
#pragma unroll
    for (int nt2 = 0; nt2 < 2; nt2++) {
        const int rt = lane & 7, tl = lane >> 3;
        const int n = nBase + nt2 * 16 + ((tl >> 1) << 3) + rt;
        boff[nt2] = (uint32_t)(n * PITCHB + (tl & 1) * 16);
    }

    for (int tt = 0; tt < TCH_T; tt++) {
        const int t = tbase + tt;

        // Stage X tile [128 b x 128 d] hi/lo
        for (int i = tid; i < 128 * 32; i += 256) {
            const int row = i >> 5, c4 = i & 31;
            const float4 v = *reinterpret_cast<const float4*>(
                in + (size_t)row * strideB + (size_t)t * strideT + c4 * 4);
            uint2 hi, lo;
            split4(v, hi, lo);
            const int off = row * PITCHB + c4 * 8;
            *reinterpret_cast<uint2*>(smem + SM_XHI + off) = hi;
            *reinterpret_cast<uint2*>(smem + SM_XLO + off) = lo;
        }
        __syncthreads();

        float acc[4][4][4];
#pragma unroll
        for (int mt = 0; mt < 4; mt++)
#pragma unroll
            for (int nt = 0; nt < 4; nt++)
#pragma unroll
                for (int e = 0; e < 4; e++) acc[mt][nt][e] = 0.0f;

        // 3 splits: Ahi*Whi, Ahi*Wlo, Alo*Whi
#pragma unroll
        for (int s = 0; s < 3; s++) {
            const uint32_t aS = sb + (s == 2 ? SM_XLO : SM_XHI);
            const uint32_t bS = sb + (s == 1 ? SM_WLO : SM_WHI);
#pragma unroll
            for (int k16 = 0; k16 < 8; k16++) {
                const uint32_t kb = (uint32_t)(k16 * 32);   // 16 elems * 2B
                uint32_t a[4][4], b[2][4];
#pragma unroll
                for (int mt = 0; mt < 4; mt++) ldmx4(a[mt], aS + aoff[mt] + kb);
#pragma unroll
                for (int nt2 = 0; nt2 < 2; nt2++) ldmx4(b[nt2], bS + boff[nt2] + kb);
#pragma unroll
                for (int mt = 0; mt < 4; mt++)
#pragma unroll
                    for (int nt = 0; nt < 4; nt++)
                        mma_bf16(acc[mt][nt], a[mt],
                                 b[nt >> 1][(nt & 1) * 2], b[nt >> 1][(nt & 1) * 2 + 1]);
            }
        }

        // Write out D + bias
        const int mrow = lane >> 2;
        const int ncol = (lane & 3) * 2;
#pragma unroll
        for (int mt = 0; mt < 4; mt++) {
#pragma unroll
            for (int nt = 0; nt < 4; nt++) {
                const int col = nBase + nt * 8 + ncol;
                const float bv0 = sbias[col], bv1 = sbias[col + 1];
                const int row0 = mBase + mt * 16 + mrow;
                float* p0 = out + ((size_t)t * B_SZ + row0) * G_SZ + g0 + col;
                float* p1 = p0 + (size_t)8 * G_SZ;
                *reinterpret_cast<float2*>(p0) =
                    make_float2(acc[mt][nt][0] + bv0, acc[mt][nt][1] + bv1);
                *reinterpret_cast<float2*>(p1) =
                    make_float2(acc[mt][nt][2] + bv0, acc[mt][nt][3] + bv1);
            }
        }
        __syncthreads();   // before next timestep overwrites X tiles
    }
}

// ---------------------------------------------------------------------------
// Recurrent scan (exact R5 structure — proven 1.492 ms/layer).
// One CTA per batch element, 256 threads; tid = 2*j + p owns the p-th half
// (64 elems) of all three gate rows for output j; halves combined via shfl.
// ---------------------------------------------------------------------------
__global__ __launch_bounds__(256, 1)
void recur_kernel(const float* __restrict__ xp,
                  const float* __restrict__ W_hh,
                  const float* __restrict__ b_hh,
                  int write_y,
                  const float* __restrict__ W_out,
                  const float* __restrict__ b_out,
                  float* __restrict__ out)
{
    __shared__ __align__(16) float h_s[2][H_SZ];

    const int b   = blockIdx.x;
    const int tid = threadIdx.x;
    const int j   = tid >> 1;
    const int p   = tid & 1;

    unsigned long long wr[32], wz[32], wn[32];
    {
        const unsigned long long* rp = reinterpret_cast<const unsigned long long*>(
            W_hh + (size_t)j * H_SZ + p * 64);
        const unsigned long long* zp = reinterpret_cast<const unsigned long long*>(
            W_hh + (size_t)(H_SZ + j) * H_SZ + p * 64);
        const unsigned long long* np = reinterpret_cast<const unsigned long long*>(
            W_hh + (size_t)(2 * H_SZ + j) * H_SZ + p * 64);
#pragma unroll
        for (int i = 0; i < 32; i++) { wr[i] = rp[i]; wz[i] = zp[i]; wn[i] = np[i]; }
    }
    const float br = b_hh[j];
    const float bz = b_hh[H_SZ + j];
    const float bn = b_hh[2 * H_SZ + j];

    const float* xb = xp + (size_t)b * G_SZ;
    float xr = 0.f, xn = 0.f, xz = 0.f;
    if (p == 0) { xr = __ldg(xb + j); xn = __ldg(xb + 2 * H_SZ + j); }
    else        { xz = __ldg(xb + H_SZ + j); }

    float hreg = 0.0f;
    if (tid < H_SZ) h_s[0][tid] = 0.0f;
    __syncthreads();

    float* y0p = g_y0 + (size_t)b * H_SZ + j;

    for (int t = 0; t < S_LEN; t++) {
        const int cur = t & 1;
        const int nxt = cur ^ 1;

        float nxr = 0.f, nxn = 0.f, nxz = 0.f;
        if (t + 1 < S_LEN) {
            const float* q = xb + (size_t)(t + 1) * B_SZ * G_SZ;
            if (p == 0) { nxr = __ldg(q + j); nxn = __ldg(q + 2 * H_SZ + j); }
            else        { nxz = __ldg(q + H_SZ + j); }
        }

        const ulonglong2* hq =
            reinterpret_cast<const ulonglong2*>(&h_s[cur][p * 64]);
        unsigned long long ar0 = 0ull, ar1 = 0ull;
        unsigned long long az0 = 0ull, az1 = 0ull;
        unsigned long long an0 = 0ull, an1 = 0ull;
#pragma unroll
        for (int i = 0; i < 16; i++) {
            const ulonglong2 q = hq[i];
            ar0 = fma2(q.x, wr[2 * i + 0], ar0);
            ar1 = fma2(q.y, wr[2 * i + 1], ar1);
            az0 = fma2(q.x, wz[2 * i + 0], az0);
            az1 = fma2(q.y, wz[2 * i + 1], az1);
            an0 = fma2(q.x, wn[2 * i + 0], an0);
            an1 = fma2(q.y, wn[2 * i + 1], an1);
        }
        const unsigned long long sr2 = add2(ar0, ar1);
        const unsigned long long sz2 = add2(az0, az1);
        const unsigned long long sn2 = add2(an0, an1);
        float srh = lo32(sr2) + hi32(sr2);
        float szh = lo32(sz2) + hi32(sz2);
        float snh = lo32(sn2) + hi32(sn2);

        srh += __shfl_xor_sync(0xffffffffu, srh, 1);
        szh += __shfl_xor_sync(0xffffffffu, szh, 1);
        snh += __shfl_xor_sync(0xffffffffu, snh, 1);

        const float pr = xr + srh + br;
        const float pz = xz + szh + bz;
        const float rg = 1.0f / (1.0f + __expf(-pr));
        const float zg = 1.0f / (1.0f + __expf(-pz));
        const float z  = __shfl_xor_sync(0xffffffffu, zg, 1);

        if (p == 0) {
            const float hn = snh + bn;
            const float ag = fmaf(rg, hn, xn);
            const float sn = 1.0f / (1.0f + __expf(-2.0f * ag));
            const float n  = fmaf(2.0f, sn, -1.0f);
            const float hnew = fmaf(z, hreg - n, n);
            hreg = hnew;
            h_s[nxt][j] = hnew;
            if (write_y)
                y0p[(size_t)t * B_SZ * H_SZ] = hnew;
        }
        __syncthreads();

        xr = nxr; xn = nxn; xz = nxz;
    }

    if (!write_y && tid < C_SZ) {
        float acc = b_out[tid];
#pragma unroll 8
        for (int k = 0; k < H_SZ; k++)
            acc = fmaf(h_s[0][k], W_out[tid * H_SZ + k], acc);
        out[b * C_SZ + tid] = acc;
    }
}

// ---------------------------------------------------------------------------
extern "C" void kernel_launch(void* const* d_in, const int* in_sizes, int n_in,
                              void* d_out, int out_size)
{
    const float* x     = (const float*)d_in[0];
    const float* W_ih0 = (const float*)d_in[1];
    const float* W_hh0 = (const float*)d_in[2];
    const float* b_ih0 = (const float*)d_in[3];
    const float* b_hh0 = (const float*)d_in[4];
    const float* W_ih1 = (const float*)d_in[5];
    const float* W_hh1 = (const float*)d_in[6];
    const float* b_ih1 = (const float*)d_in[7];
    const float* b_hh1 = (const float*)d_in[8];
    const float* W_out = (const float*)d_in[9];
    const float* b_out = (const float*)d_in[10];
    float* out = (float*)d_out;

    void* xp_ptr = nullptr;
    void* y0_ptr = nullptr;
    cudaGetSymbolAddress(&xp_ptr, g_xp);
    cudaGetSymbolAddress(&y0_ptr, g_y0);
    float* xp = (float*)xp_ptr;
    float* y0 = (float*)y0_ptr;

    cudaFuncSetAttribute(gemm_mma_kernel,
                         cudaFuncAttributeMaxDynamicSharedMemorySize, SM_TOT);

    const dim3 gemm_grid(S_LEN / TCH_T, 3);

    // Layer 0 input projection: x is [B, S, D] -> strideB = S*D, strideT = D
    gemm_mma_kernel<<<gemm_grid, 256, SM_TOT>>>(x, W_ih0, b_ih0, xp,
                                                (long)S_LEN * H_SZ, (long)H_SZ);
    // Layer 0 recurrence (writes y0)
    recur_kernel<<<B_SZ, 256>>>(xp, W_hh0, b_hh0, 1, nullptr, nullptr, nullptr);

    // Layer 1 input projection: y0 is [(t*B + b)*H] -> strideB = H, strideT = B*H
    gemm_mma_kernel<<<gemm_grid, 256, SM_TOT>>>(y0, W_ih1, b_ih1, xp,
                                                (long)H_SZ, (long)B_SZ * H_SZ);
    // Layer 1 recurrence + fused output linear
    recur_kernel<<<B_SZ, 256>>>(xp, W_hh1, b_hh1, 0, W_out, b_out, out);
}